// round 10
// baseline (speedup 1.0000x reference)
#include <cuda_runtime.h>
#include <cuda_bf16.h>
#include <cuda_fp16.h>
#include <cstdint>
#include <cstddef>

// Problem shape (fixed by the bench)
#define M_DIM 8192
#define N_DIM 4096
#define K_DIM 4096
#define KBLK  32               // MX block size
#define KGRP  (K_DIM / KBLK)   // 128 scale groups per row

// ---------------- scratch (device globals; no allocation) ----------------
// Dequantized operands in f16 (exact representation of q_e4m3 * 2^e).
__device__ __half g_xdq[(size_t)M_DIM * K_DIM];   // 64 MB
__device__ __half g_wdq[(size_t)N_DIM * K_DIM];   // 32 MB

// ---------------- hand-rolled bit-exact e4m3 RNE quantization ----------------
// y must already be clipped to [-448, 448] (reference clips BEFORE the cast).
// e4m3: 3 mantissa bits, normals |v| in [2^-6, 448], subnormal step 2^-9.
// RNE on a power-of-two step grid via rintf (device default rounding = RNE):
//   |y| <  2^-6 : q = rintf(y * 512) / 512                    (step 2^-9)
//   |y| >= 2^-6 : step = 2^(floor(log2|y|) - 3); q = rintf(y/step)*step
__device__ __forceinline__ float quant_e4m3_rne(float y) {
    float ay = fabsf(y);
    if (ay < 0.015625f) {                       // < 2^-6 : subnormal grid
        return rintf(y * 512.0f) * (1.0f / 512.0f);
    }
    int qe = (int)((__float_as_uint(ay) >> 23) & 0xFF) - 127;   // floor(log2 ay), exact
    float step = __uint_as_float((uint32_t)(qe - 3 + 127) << 23);   // 2^(qe-3)
    return rintf(y / step) * step;
}

// ---------------- quantize+dequantize prepass (UNCHANGED from R9) -------------
__global__ void __launch_bounds__(256) quant_dq_kernel(const float* __restrict__ in,
                                                       int which, int nblk) {
    int idx = blockIdx.x * 256 + threadIdx.x;
    if (idx >= nblk) return;
    __half* __restrict__ outp = which ? g_wdq : g_xdq;

    const float4* p = reinterpret_cast<const float4*>(in) + (size_t)idx * 8;
    float4 v[8];
#pragma unroll
    for (int i = 0; i < 8; i++) v[i] = p[i];

    float amax = 1e-38f;
#pragma unroll
    for (int i = 0; i < 8; i++) {
        amax = fmaxf(amax, fabsf(v[i].x)); amax = fmaxf(amax, fabsf(v[i].y));
        amax = fmaxf(amax, fabsf(v[i].z)); amax = fmaxf(amax, fabsf(v[i].w));
    }
    int e = (int)((__float_as_uint(amax) >> 23) & 0xFF) - 127;  // floor(log2 amax), exact
    int ex = e - 8;
    ex = ex < -127 ? -127 : ex;                                  // upper clamp unreachable
    float inv = __uint_as_float((uint32_t)(127 - ex) << 23);     // 2^-ex (normal range)
    float scale = __uint_as_float((uint32_t)(ex + 127) << 23);   // 2^ex

    const float* f = reinterpret_cast<const float*>(v);
    uint32_t w[16];
#pragma unroll
    for (int j = 0; j < 16; j++) {
        float y0 = fminf(fmaxf(f[2 * j] * inv, -448.0f), 448.0f);
        float y1 = fminf(fmaxf(f[2 * j + 1] * inv, -448.0f), 448.0f);
        float dq0 = quant_e4m3_rne(y0) * scale;
        float dq1 = quant_e4m3_rne(y1) * scale;
        __half h0 = __float2half_rn(dq0);   // exact: dq on the f16 grid
        __half h1 = __float2half_rn(dq1);
        uint32_t lo = (uint32_t)*reinterpret_cast<uint16_t*>(&h0);
        uint32_t hi = (uint32_t)*reinterpret_cast<uint16_t*>(&h1);
        w[j] = lo | (hi << 16);
    }
    uint4* op = reinterpret_cast<uint4*>(outp + (size_t)idx * 32);
    op[0] = make_uint4(w[0], w[1], w[2], w[3]);
    op[1] = make_uint4(w[4], w[5], w[6], w[7]);
    op[2] = make_uint4(w[8], w[9], w[10], w[11]);
    op[3] = make_uint4(w[12], w[13], w[14], w[15]);
}

// ---------------- SIMT FFMA GEMM (UNCHANGED except f32 output) ---------------
// C[8192,4096] = A[8192,4096] * B[4096,4096]^T + bias, f32 accumulation.
// OUTPUT: float32, each value rounded to bf16 first (checker compares against
// the reference's bf16 result upcast to f32).
#define ST 128
#define SK 16
#define NKT (K_DIM / SK)   // 256 k-steps

__global__ void __launch_bounds__(256, 2)
simt_gemm(const float* __restrict__ bias, float* __restrict__ out) {
    __shared__ float As[SK][ST];   // As[k][m]
    __shared__ float Bs[SK][ST];   // Bs[k][n]
    int tid = threadIdx.x;
    int tx = tid & 15, ty = tid >> 4;
    int ntile = blockIdx.x, mtile = blockIdx.y;

    const __half* Ag = g_xdq + (size_t)(mtile * ST) * K_DIM;
    const __half* Bg = g_wdq + (size_t)(ntile * ST) * K_DIM;

    float acc[8][8];
#pragma unroll
    for (int i = 0; i < 8; i++)
#pragma unroll
        for (int j = 0; j < 8; j++) acc[i][j] = 0.f;

    __half2 ra[4], rb[4];

#define LOADG(kt)                                                                     \
    do {                                                                              \
        _Pragma("unroll")                                                             \
        for (int i_ = 0; i_ < 4; i_++) {                                              \
            int h_ = tid * 4 + i_;                                                    \
            int r_ = h_ >> 3, c2_ = h_ & 7;                                           \
            ra[i_] = *reinterpret_cast<const __half2*>(                               \
                Ag + (size_t)r_ * K_DIM + (kt) * SK + c2_ * 2);                       \
            rb[i_] = *reinterpret_cast<const __half2*>(                               \
                Bg + (size_t)r_ * K_DIM + (kt) * SK + c2_ * 2);                       \
        }                                                                             \
    } while (0)

#define STORE_SMEM()                                                                  \
    do {                                                                              \
        _Pragma("unroll")                                                             \
        for (int i_ = 0; i_ < 4; i_++) {                                              \
            int h_ = tid * 4 + i_;                                                    \
            int r_ = h_ >> 3, c2_ = h_ & 7;                                           \
            float2 fa_ = __half22float2(ra[i_]);                                      \
            float2 fb_ = __half22float2(rb[i_]);                                      \
            As[2 * c2_][r_] = fa_.x; As[2 * c2_ + 1][r_] = fa_.y;                     \
            Bs[2 * c2_][r_] = fb_.x; Bs[2 * c2_ + 1][r_] = fb_.y;                     \
        }                                                                             \
    } while (0)

    LOADG(0);
    for (int kt = 0; kt < NKT; kt++) {
        STORE_SMEM();
        __syncthreads();
        if (kt + 1 < NKT) LOADG(kt + 1);   // overlap next gmem fetch with compute
#pragma unroll
        for (int kk = 0; kk < SK; kk++) {
            float4 a0 = *reinterpret_cast<const float4*>(&As[kk][ty * 8]);
            float4 a1 = *reinterpret_cast<const float4*>(&As[kk][ty * 8 + 4]);
            float4 b0 = *reinterpret_cast<const float4*>(&Bs[kk][tx * 8]);
            float4 b1 = *reinterpret_cast<const float4*>(&Bs[kk][tx * 8 + 4]);
            float av[8] = {a0.x, a0.y, a0.z, a0.w, a1.x, a1.y, a1.z, a1.w};
            float bv[8] = {b0.x, b0.y, b0.z, b0.w, b1.x, b1.y, b1.z, b1.w};
#pragma unroll
            for (int i = 0; i < 8; i++)
#pragma unroll
                for (int j = 0; j < 8; j++) acc[i][j] = fmaf(av[i], bv[j], acc[i][j]);
        }
        __syncthreads();
    }

    // ---- epilogue: + bias -> round to bf16 grid -> store as f32 ----
    int m0 = mtile * ST + ty * 8;
    int n0 = ntile * ST + tx * 8;
    float bvv[8];
#pragma unroll
    for (int j = 0; j < 8; j++) bvv[j] = bias[n0 + j];
#pragma unroll
    for (int i = 0; i < 8; i++) {
        float o[8];
#pragma unroll
        for (int j = 0; j < 8; j++) {
            __nv_bfloat16 b16 = __float2bfloat16_rn(acc[i][j] + bvv[j]);
            o[j] = __bfloat162float(b16);
        }
        float4* op = reinterpret_cast<float4*>(out + (size_t)(m0 + i) * N_DIM + n0);
        op[0] = make_float4(o[0], o[1], o[2], o[3]);
        op[1] = make_float4(o[4], o[5], o[6], o[7]);
    }
}

// ---------------- launch ----------------
extern "C" void kernel_launch(void* const* d_in, const int* in_sizes, int n_in,
                              void* d_out, int out_size) {
    (void)out_size;
    // Identify inputs by element count (robust to metadata ordering):
    //   x: 8192*4096 = 33,554,432 ; weight: 4096*4096 = 16,777,216 ; bias: 4096
    const float* x = nullptr;
    const float* w = nullptr;
    const float* bias = nullptr;
    for (int i = 0; i < n_in; i++) {
        if (in_sizes[i] == 33554432) x = (const float*)d_in[i];
        else if (in_sizes[i] == 16777216) w = (const float*)d_in[i];
        else if (in_sizes[i] == 4096) bias = (const float*)d_in[i];
    }
    if (!x) x = (const float*)d_in[0];
    if (!w) w = (const float*)d_in[1];
    if (!bias) bias = (const float*)d_in[2];
    float* out = (float*)d_out;   // f32 output (bf16-rounded values)

    quant_dq_kernel<<<(M_DIM * KGRP) / 256, 256>>>(x, 0, M_DIM * KGRP);
    quant_dq_kernel<<<(N_DIM * KGRP) / 256, 256>>>(w, 1, N_DIM * KGRP);

    dim3 grid(N_DIM / ST, M_DIM / ST);   // 32 x 64
    simt_gemm<<<grid, 256>>>(bias, out);
}

// round 11
// speedup vs baseline: 7.8650x; 7.8650x over previous
#include <cuda_runtime.h>
#include <cuda_bf16.h>
#include <cuda_fp16.h>
#include <cstdint>
#include <cstddef>

// Problem shape (fixed by the bench)
#define M_DIM 8192
#define N_DIM 4096
#define K_DIM 4096
#define KBLK  32               // MX block size
#define KGRP  (K_DIM / KBLK)   // 128 scale groups per row

// ---------------- scratch (device globals; no allocation) ----------------
// Dequantized operands in f16 (exact representation of q_e4m3 * 2^e).
__device__ __half g_xdq[(size_t)M_DIM * K_DIM];   // 64 MB
__device__ __half g_wdq[(size_t)N_DIM * K_DIM];   // 32 MB

// ---------------- helpers ----------------
__device__ __forceinline__ uint32_t smem_u32(const void* p) {
    uint32_t a;
    asm("{ .reg .u64 t; cvta.to.shared.u64 t, %1; cvt.u32.u64 %0, t; }" : "=r"(a) : "l"(p));
    return a;
}
__device__ __forceinline__ void cp_async16(uint32_t smem, const void* gmem) {
    asm volatile("cp.async.cg.shared.global [%0], [%1], 16;" :: "r"(smem), "l"(gmem) : "memory");
}
__device__ __forceinline__ void mma16816(float* c, const uint32_t* a, const uint32_t* b) {
    asm volatile(
        "mma.sync.aligned.m16n8k16.row.col.f32.f16.f16.f32 "
        "{%0,%1,%2,%3}, {%4,%5,%6,%7}, {%8,%9}, {%0,%1,%2,%3};"
        : "+f"(c[0]), "+f"(c[1]), "+f"(c[2]), "+f"(c[3])
        : "r"(a[0]), "r"(a[1]), "r"(a[2]), "r"(a[3]), "r"(b[0]), "r"(b[1]));
}

// ---------------- hand-rolled bit-exact e4m3 RNE quantization (PROVEN R10) ----
__device__ __forceinline__ float quant_e4m3_rne(float y) {
    float ay = fabsf(y);
    if (ay < 0.015625f) {                       // < 2^-6 : subnormal grid
        return rintf(y * 512.0f) * (1.0f / 512.0f);
    }
    int qe = (int)((__float_as_uint(ay) >> 23) & 0xFF) - 127;   // floor(log2 ay), exact
    float step = __uint_as_float((uint32_t)(qe - 3 + 127) << 23);   // 2^(qe-3)
    return rintf(y / step) * step;
}

// ---------------- quantize+dequantize prepass (PROVEN R10, unchanged) ---------
__global__ void __launch_bounds__(256) quant_dq_kernel(const float* __restrict__ in,
                                                       int which, int nblk) {
    int idx = blockIdx.x * 256 + threadIdx.x;
    if (idx >= nblk) return;
    __half* __restrict__ outp = which ? g_wdq : g_xdq;

    const float4* p = reinterpret_cast<const float4*>(in) + (size_t)idx * 8;
    float4 v[8];
#pragma unroll
    for (int i = 0; i < 8; i++) v[i] = p[i];

    float amax = 1e-38f;
#pragma unroll
    for (int i = 0; i < 8; i++) {
        amax = fmaxf(amax, fabsf(v[i].x)); amax = fmaxf(amax, fabsf(v[i].y));
        amax = fmaxf(amax, fabsf(v[i].z)); amax = fmaxf(amax, fabsf(v[i].w));
    }
    int e = (int)((__float_as_uint(amax) >> 23) & 0xFF) - 127;  // floor(log2 amax), exact
    int ex = e - 8;
    ex = ex < -127 ? -127 : ex;                                  // upper clamp unreachable
    float inv = __uint_as_float((uint32_t)(127 - ex) << 23);     // 2^-ex (normal range)
    float scale = __uint_as_float((uint32_t)(ex + 127) << 23);   // 2^ex

    const float* f = reinterpret_cast<const float*>(v);
    uint32_t w[16];
#pragma unroll
    for (int j = 0; j < 16; j++) {
        float y0 = fminf(fmaxf(f[2 * j] * inv, -448.0f), 448.0f);
        float y1 = fminf(fmaxf(f[2 * j + 1] * inv, -448.0f), 448.0f);
        float dq0 = quant_e4m3_rne(y0) * scale;
        float dq1 = quant_e4m3_rne(y1) * scale;
        __half h0 = __float2half_rn(dq0);   // exact: dq on the f16 grid
        __half h1 = __float2half_rn(dq1);
        uint32_t lo = (uint32_t)*reinterpret_cast<uint16_t*>(&h0);
        uint32_t hi = (uint32_t)*reinterpret_cast<uint16_t*>(&h1);
        w[j] = lo | (hi << 16);
    }
    uint4* op = reinterpret_cast<uint4*>(outp + (size_t)idx * 32);
    op[0] = make_uint4(w[0], w[1], w[2], w[3]);
    op[1] = make_uint4(w[4], w[5], w[6], w[7]);
    op[2] = make_uint4(w[8], w[9], w[10], w[11]);
    op[3] = make_uint4(w[12], w[13], w[14], w[15]);
}

// ---------------- tensor-core GEMM (R5 machinery + PROVEN epilogue) -----------
// C[8192,4096] = A[8192,4096] * B[4096,4096]^T + bias.
// CTA tile 256(M) x 128(N), 256 threads (8 warps as 4x2, warp tile 64x64).
// K-chunk = 64 halves; padded smem rows RS=144B; manual per-lane LDS fragments
// straight from the PTX mma.m16n8k16 fragment tables; 4-stage cp.async pipeline.
// OUTPUT: float32 values pre-rounded to the bf16 grid (proven convention).
#define TM 256
#define TN 128
#define KC 64
#define NCHUNK (K_DIM / KC)          // 64
#define RS 144                        // smem row stride in bytes
#define STAGE_A_BYTES (TM * RS)      // 36864
#define STAGE_B_BYTES (TN * RS)      // 18432
#define STAGE_BYTES (STAGE_A_BYTES + STAGE_B_BYTES)  // 55296
#define GEMM_SMEM (4 * STAGE_BYTES)                  // 221184 (216 KB)

__global__ void __launch_bounds__(256, 1)
mx_gemm_f16(const float* __restrict__ bias, float* __restrict__ out) {
    extern __shared__ char smem[];
    uint32_t sb = smem_u32(smem);
    int tid = threadIdx.x;
    int lane = tid & 31;
    int wid = tid >> 5;
    int wm = wid & 3;      // 4 M-groups of 64
    int wn = wid >> 2;     // 2 N-groups of 64
    int g = lane >> 2;     // groupID (PTX fragment tables)
    int t = lane & 3;      // threadID_in_group
    int mtile = blockIdx.x, ntile = blockIdx.y;

    const char* Ab = (const char*)(g_xdq + (size_t)mtile * TM * K_DIM);
    const char* Bb = (const char*)(g_wdq + (size_t)ntile * TN * K_DIM);

    float acc[4][8][4];
#pragma unroll
    for (int i = 0; i < 4; i++)
#pragma unroll
        for (int j = 0; j < 8; j++)
#pragma unroll
            for (int k = 0; k < 4; k++) acc[i][j][k] = 0.f;

    // ---- async stage loader (dst = row*RS + seg*16, 128B payload per row) ----
#define LOAD_STAGE(chunk, s)                                                            \
    do {                                                                                \
        uint32_t sa_ = sb + (s) * STAGE_BYTES;                                          \
        const char* ag_ = Ab + (size_t)(chunk) * 128;                                   \
        _Pragma("unroll")                                                               \
        for (int i_ = 0; i_ < 8; i_++) {                                                \
            int idx_ = tid + i_ * 256;                                                  \
            int row_ = idx_ >> 3, seg_ = idx_ & 7;                                      \
            cp_async16(sa_ + (uint32_t)(row_ * RS + seg_ * 16),                         \
                       ag_ + (size_t)row_ * (K_DIM * 2) + seg_ * 16);                   \
        }                                                                               \
        uint32_t sbm_ = sa_ + STAGE_A_BYTES;                                            \
        const char* bg_ = Bb + (size_t)(chunk) * 128;                                   \
        _Pragma("unroll")                                                               \
        for (int i_ = 0; i_ < 4; i_++) {                                                \
            int idx_ = tid + i_ * 256;                                                  \
            int row_ = idx_ >> 3, seg_ = idx_ & 7;                                      \
            cp_async16(sbm_ + (uint32_t)(row_ * RS + seg_ * 16),                        \
                       bg_ + (size_t)row_ * (K_DIM * 2) + seg_ * 16);                   \
        }                                                                               \
        asm volatile("cp.async.commit_group;" ::: "memory");                            \
    } while (0)

    // prologue: chunks 0..2 into stages 0..2
    LOAD_STAGE(0, 0);
    LOAD_STAGE(1, 1);
    LOAD_STAGE(2, 2);

    for (int c = 0; c < NCHUNK; c++) {
        int pf = c + 3;
        if (pf < NCHUNK) {
            LOAD_STAGE(pf, pf & 3);
        } else {
            asm volatile("cp.async.commit_group;" ::: "memory");
        }
        asm volatile("cp.async.wait_group 3;" ::: "memory");
        __syncthreads();

        const char* sp = smem + (size_t)(c & 3) * STAGE_BYTES;
#pragma unroll
        for (int kb = 0; kb < 4; kb++) {
            int kbyte = t * 4 + kb * 32;   // this lane's k-pair byte offset within the row
            // A fragments, PTX table m16n8k16.A (row-major m16 x k16):
            //   reg0: (m=g,   k=2t,2t+1)   reg1: (m=g+8, k=2t,2t+1)
            //   reg2: (m=g,   k=2t+8,+9)   reg3: (m=g+8, k=2t+8,+9)
            uint32_t a[4][4];
#pragma unroll
            for (int mf = 0; mf < 4; mf++) {
                const char* ra = sp + (wm * 64 + mf * 16 + g) * RS + kbyte;
                a[mf][0] = *reinterpret_cast<const uint32_t*>(ra);
                a[mf][1] = *reinterpret_cast<const uint32_t*>(ra + 8 * RS);
                a[mf][2] = *reinterpret_cast<const uint32_t*>(ra + 16);
                a[mf][3] = *reinterpret_cast<const uint32_t*>(ra + 8 * RS + 16);
            }
            // B fragments, PTX table m16n8k16.B (col-major k16 x n8); smem holds W as [n][k]:
            //   reg0: (k=2t,2t+1, n=g)    reg1: (k=2t+8,+9, n=g)
            uint32_t b[8][2];
#pragma unroll
            for (int jp = 0; jp < 4; jp++) {
                const char* rb = sp + STAGE_A_BYTES + (wn * 64 + jp * 16 + g) * RS + kbyte;
                b[2 * jp][0]     = *reinterpret_cast<const uint32_t*>(rb);
                b[2 * jp][1]     = *reinterpret_cast<const uint32_t*>(rb + 16);
                b[2 * jp + 1][0] = *reinterpret_cast<const uint32_t*>(rb + 8 * RS);
                b[2 * jp + 1][1] = *reinterpret_cast<const uint32_t*>(rb + 8 * RS + 16);
            }
#pragma unroll
            for (int mf = 0; mf < 4; mf++)
#pragma unroll
                for (int nf = 0; nf < 8; nf++) mma16816(acc[mf][nf], a[mf], b[nf]);
        }
        __syncthreads();
    }

    // ---- epilogue: + bias -> round to bf16 grid -> store f32 (PROVEN) ----
    // PTX table m16n8k16.C: reg0,1 at (m=g, n=2t,2t+1); reg2,3 at (m=g+8, same n).
    int ncol0 = ntile * TN + wn * 64 + t * 2;
    float2 bv[8];
#pragma unroll
    for (int nf = 0; nf < 8; nf++)
        bv[nf] = *reinterpret_cast<const float2*>(bias + ncol0 + nf * 8);

    size_t mrow0 = (size_t)mtile * TM + wm * 64 + g;
#pragma unroll
    for (int mf = 0; mf < 4; mf++) {
        size_t r0 = mrow0 + mf * 16;
        size_t r1 = r0 + 8;
#pragma unroll
        for (int nf = 0; nf < 8; nf++) {
            int n = ncol0 + nf * 8;
            float o0 = __bfloat162float(__float2bfloat16_rn(acc[mf][nf][0] + bv[nf].x));
            float o1 = __bfloat162float(__float2bfloat16_rn(acc[mf][nf][1] + bv[nf].y));
            float o2 = __bfloat162float(__float2bfloat16_rn(acc[mf][nf][2] + bv[nf].x));
            float o3 = __bfloat162float(__float2bfloat16_rn(acc[mf][nf][3] + bv[nf].y));
            *reinterpret_cast<float2*>(out + r0 * N_DIM + n) = make_float2(o0, o1);
            *reinterpret_cast<float2*>(out + r1 * N_DIM + n) = make_float2(o2, o3);
        }
    }
}

// ---------------- launch ----------------
extern "C" void kernel_launch(void* const* d_in, const int* in_sizes, int n_in,
                              void* d_out, int out_size) {
    (void)out_size;
    // Identify inputs by element count (robust to metadata ordering):
    //   x: 8192*4096 = 33,554,432 ; weight: 4096*4096 = 16,777,216 ; bias: 4096
    const float* x = nullptr;
    const float* w = nullptr;
    const float* bias = nullptr;
    for (int i = 0; i < n_in; i++) {
        if (in_sizes[i] == 33554432) x = (const float*)d_in[i];
        else if (in_sizes[i] == 16777216) w = (const float*)d_in[i];
        else if (in_sizes[i] == 4096) bias = (const float*)d_in[i];
    }
    if (!x) x = (const float*)d_in[0];
    if (!w) w = (const float*)d_in[1];
    if (!bias) bias = (const float*)d_in[2];
    float* out = (float*)d_out;   // f32 output (bf16-rounded values) — PROVEN

    cudaFuncSetAttribute(mx_gemm_f16, cudaFuncAttributeMaxDynamicSharedMemorySize, GEMM_SMEM);

    quant_dq_kernel<<<(M_DIM * KGRP) / 256, 256>>>(x, 0, M_DIM * KGRP);
    quant_dq_kernel<<<(N_DIM * KGRP) / 256, 256>>>(w, 1, N_DIM * KGRP);

    dim3 grid(M_DIM / TM, N_DIM / TN);   // 32 x 32
    mx_gemm_f16<<<grid, 256, GEMM_SMEM>>>(bias, out);
}

// round 12
// speedup vs baseline: 7.9161x; 1.0065x over previous
#include <cuda_runtime.h>
#include <cuda_bf16.h>
#include <cuda_fp16.h>
#include <cstdint>
#include <cstddef>

// Problem shape (fixed by the bench)
#define M_DIM 8192
#define N_DIM 4096
#define K_DIM 4096
#define KBLK  32               // MX block size
#define KGRP  (K_DIM / KBLK)   // 128 scale groups per row

// ---------------- scratch (device globals; no allocation) ----------------
// Dequantized operands in f16 (exact representation of q_e4m3 * 2^e).
__device__ __half g_xdq[(size_t)M_DIM * K_DIM];   // 64 MB
__device__ __half g_wdq[(size_t)N_DIM * K_DIM];   // 32 MB

// ---------------- helpers ----------------
__device__ __forceinline__ uint32_t smem_u32(const void* p) {
    uint32_t a;
    asm("{ .reg .u64 t; cvta.to.shared.u64 t, %1; cvt.u32.u64 %0, t; }" : "=r"(a) : "l"(p));
    return a;
}
__device__ __forceinline__ void cp_async16(uint32_t smem, const void* gmem) {
    asm volatile("cp.async.cg.shared.global [%0], [%1], 16;" :: "r"(smem), "l"(gmem) : "memory");
}
__device__ __forceinline__ void ldsm_x4(uint32_t& r0, uint32_t& r1, uint32_t& r2, uint32_t& r3,
                                        uint32_t addr) {
    asm volatile("ldmatrix.sync.aligned.m8n8.x4.shared.b16 {%0,%1,%2,%3}, [%4];"
                 : "=r"(r0), "=r"(r1), "=r"(r2), "=r"(r3) : "r"(addr) : "memory");
}
__device__ __forceinline__ void mma16816(float* c, const uint32_t* a, const uint32_t* b) {
    asm volatile(
        "mma.sync.aligned.m16n8k16.row.col.f32.f16.f16.f32 "
        "{%0,%1,%2,%3}, {%4,%5,%6,%7}, {%8,%9}, {%0,%1,%2,%3};"
        : "+f"(c[0]), "+f"(c[1]), "+f"(c[2]), "+f"(c[3])
        : "r"(a[0]), "r"(a[1]), "r"(a[2]), "r"(a[3]), "r"(b[0]), "r"(b[1]));
}

// ---------------- hand-rolled bit-exact e4m3 RNE quantization (PROVEN) --------
__device__ __forceinline__ float quant_e4m3_rne(float y) {
    float ay = fabsf(y);
    if (ay < 0.015625f) {                       // < 2^-6 : subnormal grid
        return rintf(y * 512.0f) * (1.0f / 512.0f);
    }
    int qe = (int)((__float_as_uint(ay) >> 23) & 0xFF) - 127;   // floor(log2 ay), exact
    float step = __uint_as_float((uint32_t)(qe - 3 + 127) << 23);   // 2^(qe-3)
    return rintf(y / step) * step;
}

// ---------------- quantize+dequantize prepass (PROVEN, unchanged) -------------
__global__ void __launch_bounds__(256) quant_dq_kernel(const float* __restrict__ in,
                                                       int which, int nblk) {
    int idx = blockIdx.x * 256 + threadIdx.x;
    if (idx >= nblk) return;
    __half* __restrict__ outp = which ? g_wdq : g_xdq;

    const float4* p = reinterpret_cast<const float4*>(in) + (size_t)idx * 8;
    float4 v[8];
#pragma unroll
    for (int i = 0; i < 8; i++) v[i] = p[i];

    float amax = 1e-38f;
#pragma unroll
    for (int i = 0; i < 8; i++) {
        amax = fmaxf(amax, fabsf(v[i].x)); amax = fmaxf(amax, fabsf(v[i].y));
        amax = fmaxf(amax, fabsf(v[i].z)); amax = fmaxf(amax, fabsf(v[i].w));
    }
    int e = (int)((__float_as_uint(amax) >> 23) & 0xFF) - 127;  // floor(log2 amax), exact
    int ex = e - 8;
    ex = ex < -127 ? -127 : ex;                                  // upper clamp unreachable
    float inv = __uint_as_float((uint32_t)(127 - ex) << 23);     // 2^-ex (normal range)
    float scale = __uint_as_float((uint32_t)(ex + 127) << 23);   // 2^ex

    const float* f = reinterpret_cast<const float*>(v);
    uint32_t w[16];
#pragma unroll
    for (int j = 0; j < 16; j++) {
        float y0 = fminf(fmaxf(f[2 * j] * inv, -448.0f), 448.0f);
        float y1 = fminf(fmaxf(f[2 * j + 1] * inv, -448.0f), 448.0f);
        float dq0 = quant_e4m3_rne(y0) * scale;
        float dq1 = quant_e4m3_rne(y1) * scale;
        __half h0 = __float2half_rn(dq0);   // exact: dq on the f16 grid
        __half h1 = __float2half_rn(dq1);
        uint32_t lo = (uint32_t)*reinterpret_cast<uint16_t*>(&h0);
        uint32_t hi = (uint32_t)*reinterpret_cast<uint16_t*>(&h1);
        w[j] = lo | (hi << 16);
    }
    uint4* op = reinterpret_cast<uint4*>(outp + (size_t)idx * 32);
    op[0] = make_uint4(w[0], w[1], w[2], w[3]);
    op[1] = make_uint4(w[4], w[5], w[6], w[7]);
    op[2] = make_uint4(w[8], w[9], w[10], w[11]);
    op[3] = make_uint4(w[12], w[13], w[14], w[15]);
}

// ---------------- tensor-core GEMM: ldmatrix fragment path --------------------
// C[8192,4096] = A[8192,4096] * B[4096,4096]^T + bias.
// CTA tile 256(M) x 128(N), 256 threads (8 warps as 4x2, warp tile 64x64).
// K-chunk = 64 halves; padded smem rows RS=144B (no swizzle); ldmatrix.x4
// fragments (proven equivalent to the manual-LDS path); 4-stage cp.async pipe.
// OUTPUT: float32 values pre-rounded to the bf16 grid (proven convention).
#define TM 256
#define TN 128
#define KC 64
#define NCHUNK (K_DIM / KC)          // 64
#define RS 144                        // smem row stride in bytes
#define STAGE_A_BYTES (TM * RS)      // 36864
#define STAGE_B_BYTES (TN * RS)      // 18432
#define STAGE_BYTES (STAGE_A_BYTES + STAGE_B_BYTES)  // 55296
#define GEMM_SMEM (4 * STAGE_BYTES)                  // 221184 (216 KB)

__global__ void __launch_bounds__(256, 1)
mx_gemm_f16(const float* __restrict__ bias, float* __restrict__ out) {
    extern __shared__ char smem[];
    uint32_t sb = smem_u32(smem);
    int tid = threadIdx.x;
    int lane = tid & 31;
    int wid = tid >> 5;
    int wm = wid & 3;      // 4 M-groups of 64
    int wn = wid >> 2;     // 2 N-groups of 64
    int mtile = blockIdx.x, ntile = blockIdx.y;

    const char* Ab = (const char*)(g_xdq + (size_t)mtile * TM * K_DIM);
    const char* Bb = (const char*)(g_wdq + (size_t)ntile * TN * K_DIM);

    // ldmatrix.x4 lane->address mapping (proven equivalent to manual-LDS R5):
    // A (m16 x k16): lanes 0-15 -> rows m0-15 (matrices 0,1: k0-7),
    //                lanes 16-31 -> rows m0-15 at +16B (matrices 2,3: k8-15)
    //   regs r0..r3 = a0..a3 of the mma A fragment.
    // B (n16 x k16): lanes 0-7 n0-7/k0-7, 8-15 n0-7/k8-15,
    //                16-23 n8-15/k0-7, 24-31 n8-15/k8-15
    //   r0,r1 = b of n-group 0; r2,r3 = b of n-group 1.
    uint32_t abase[4], bbase[4];
    {
        int arow_l = lane & 15;
        int aseg = (lane >> 4) & 1;
#pragma unroll
        for (int mf = 0; mf < 4; mf++)
            abase[mf] = (uint32_t)((wm * 64 + mf * 16 + arow_l) * RS + aseg * 16);
        int brow_l = (lane & 7) + ((lane & 16) ? 8 : 0);
        int bseg = (lane >> 3) & 1;
#pragma unroll
        for (int jp = 0; jp < 4; jp++)
            bbase[jp] = (uint32_t)(STAGE_A_BYTES + (wn * 64 + jp * 16 + brow_l) * RS + bseg * 16);
    }

    float acc[4][8][4];
#pragma unroll
    for (int i = 0; i < 4; i++)
#pragma unroll
        for (int j = 0; j < 8; j++)
#pragma unroll
            for (int k = 0; k < 4; k++) acc[i][j][k] = 0.f;

    // ---- async stage loader (dst = row*RS + seg*16, 128B payload per row) ----
#define LOAD_STAGE(chunk, s)                                                            \
    do {                                                                                \
        uint32_t sa_ = sb + (s) * STAGE_BYTES;                                          \
        const char* ag_ = Ab + (size_t)(chunk) * 128;                                   \
        _Pragma("unroll")                                                               \
        for (int i_ = 0; i_ < 8; i_++) {                                                \
            int idx_ = tid + i_ * 256;                                                  \
            int row_ = idx_ >> 3, seg_ = idx_ & 7;                                      \
            cp_async16(sa_ + (uint32_t)(row_ * RS + seg_ * 16),                         \
                       ag_ + (size_t)row_ * (K_DIM * 2) + seg_ * 16);                   \
        }                                                                               \
        uint32_t sbm_ = sa_ + STAGE_A_BYTES;                                            \
        const char* bg_ = Bb + (size_t)(chunk) * 128;                                   \
        _Pragma("unroll")                                                               \
        for (int i_ = 0; i_ < 4; i_++) {                                                \
            int idx_ = tid + i_ * 256;                                                  \
            int row_ = idx_ >> 3, seg_ = idx_ & 7;                                      \
            cp_async16(sbm_ + (uint32_t)(row_ * RS + seg_ * 16),                        \
                       bg_ + (size_t)row_ * (K_DIM * 2) + seg_ * 16);                   \
        }                                                                               \
        asm volatile("cp.async.commit_group;" ::: "memory");                            \
    } while (0)

    // prologue: chunks 0..2 into stages 0..2
    LOAD_STAGE(0, 0);
    LOAD_STAGE(1, 1);
    LOAD_STAGE(2, 2);

    for (int c = 0; c < NCHUNK; c++) {
        int pf = c + 3;
        if (pf < NCHUNK) {
            LOAD_STAGE(pf, pf & 3);
        } else {
            asm volatile("cp.async.commit_group;" ::: "memory");
        }
        asm volatile("cp.async.wait_group 3;" ::: "memory");
        __syncthreads();

        uint32_t sa = sb + (uint32_t)(c & 3) * STAGE_BYTES;
#pragma unroll
        for (int kb = 0; kb < 4; kb++) {
            uint32_t kx = (uint32_t)(kb * 32);   // plain add: padded rows, no swizzle
            uint32_t a[4][4];
#pragma unroll
            for (int mf = 0; mf < 4; mf++)
                ldsm_x4(a[mf][0], a[mf][1], a[mf][2], a[mf][3], sa + abase[mf] + kx);
            uint32_t b[8][2];
#pragma unroll
            for (int jp = 0; jp < 4; jp++) {
                uint32_t r0, r1, r2, r3;
                ldsm_x4(r0, r1, r2, r3, sa + bbase[jp] + kx);
                b[2 * jp][0] = r0; b[2 * jp][1] = r1;
                b[2 * jp + 1][0] = r2; b[2 * jp + 1][1] = r3;
            }
#pragma unroll
            for (int mf = 0; mf < 4; mf++)
#pragma unroll
                for (int nf = 0; nf < 8; nf++) mma16816(acc[mf][nf], a[mf], b[nf]);
        }
        __syncthreads();
    }

    // ---- epilogue: + bias -> round to bf16 grid -> store f32 (PROVEN) ----
    // PTX table m16n8k16.C: reg0,1 at (m=g, n=2t,2t+1); reg2,3 at (m=g+8, same n).
    int g = lane >> 2;
    int t = lane & 3;
    int ncol0 = ntile * TN + wn * 64 + t * 2;
    float2 bv[8];
#pragma unroll
    for (int nf = 0; nf < 8; nf++)
        bv[nf] = *reinterpret_cast<const float2*>(bias + ncol0 + nf * 8);

    size_t mrow0 = (size_t)mtile * TM + wm * 64 + g;
#pragma unroll
    for (int mf = 0; mf < 4; mf++) {
        size_t r0 = mrow0 + mf * 16;
        size_t r1 = r0 + 8;
#pragma unroll
        for (int nf = 0; nf < 8; nf++) {
            int n = ncol0 + nf * 8;
            float o0 = __bfloat162float(__float2bfloat16_rn(acc[mf][nf][0] + bv[nf].x));
            float o1 = __bfloat162float(__float2bfloat16_rn(acc[mf][nf][1] + bv[nf].y));
            float o2 = __bfloat162float(__float2bfloat16_rn(acc[mf][nf][2] + bv[nf].x));
            float o3 = __bfloat162float(__float2bfloat16_rn(acc[mf][nf][3] + bv[nf].y));
            *reinterpret_cast<float2*>(out + r0 * N_DIM + n) = make_float2(o0, o1);
            *reinterpret_cast<float2*>(out + r1 * N_DIM + n) = make_float2(o2, o3);
        }
    }
}

// ---------------- launch ----------------
extern "C" void kernel_launch(void* const* d_in, const int* in_sizes, int n_in,
                              void* d_out, int out_size) {
    (void)out_size;
    // Identify inputs by element count (robust to metadata ordering):
    //   x: 8192*4096 = 33,554,432 ; weight: 4096*4096 = 16,777,216 ; bias: 4096
    const float* x = nullptr;
    const float* w = nullptr;
    const float* bias = nullptr;
    for (int i = 0; i < n_in; i++) {
        if (in_sizes[i] == 33554432) x = (const float*)d_in[i];
        else if (in_sizes[i] == 16777216) w = (const float*)d_in[i];
        else if (in_sizes[i] == 4096) bias = (const float*)d_in[i];
    }
    if (!x) x = (const float*)d_in[0];
    if (!w) w = (const float*)d_in[1];
    if (!bias) bias = (const float*)d_in[2];
    float* out = (float*)d_out;   // f32 output (bf16-rounded values) — PROVEN

    cudaFuncSetAttribute(mx_gemm_f16, cudaFuncAttributeMaxDynamicSharedMemorySize, GEMM_SMEM);

    quant_dq_kernel<<<(M_DIM * KGRP) / 256, 256>>>(x, 0, M_DIM * KGRP);
    quant_dq_kernel<<<(N_DIM * KGRP) / 256, 256>>>(w, 1, N_DIM * KGRP);

    dim3 grid(M_DIM / TM, N_DIM / TN);   // 32 x 32
    mx_gemm_f16<<<grid, 256, GEMM_SMEM>>>(bias, out);
}

// round 13
// speedup vs baseline: 8.9958x; 1.1364x over previous
#include <cuda_runtime.h>
#include <cuda_bf16.h>
#include <cuda_fp16.h>
#include <cstdint>
#include <cstddef>

// Problem shape (fixed by the bench)
#define M_DIM 8192
#define N_DIM 4096
#define K_DIM 4096
#define KBLK  32               // MX block size
#define KGRP  (K_DIM / KBLK)   // 128 scale groups per row

// ---------------- scratch (device globals; no allocation) ----------------
__device__ __half g_xdq[(size_t)M_DIM * K_DIM];   // 64 MB
__device__ __half g_wdq[(size_t)N_DIM * K_DIM];   // 32 MB

// ---------------- helpers ----------------
__device__ __forceinline__ uint32_t smem_u32(const void* p) {
    uint32_t a;
    asm("{ .reg .u64 t; cvta.to.shared.u64 t, %1; cvt.u32.u64 %0, t; }" : "=r"(a) : "l"(p));
    return a;
}
__device__ __forceinline__ void cp_async16(uint32_t smem, const void* gmem) {
    asm volatile("cp.async.cg.shared.global [%0], [%1], 16;" :: "r"(smem), "l"(gmem) : "memory");
}
__device__ __forceinline__ void ldsm_x4(uint32_t& r0, uint32_t& r1, uint32_t& r2, uint32_t& r3,
                                        uint32_t addr) {
    asm volatile("ldmatrix.sync.aligned.m8n8.x4.shared.b16 {%0,%1,%2,%3}, [%4];"
                 : "=r"(r0), "=r"(r1), "=r"(r2), "=r"(r3) : "r"(addr) : "memory");
}
__device__ __forceinline__ void mma16816(float* c, const uint32_t* a, const uint32_t* b) {
    asm volatile(
        "mma.sync.aligned.m16n8k16.row.col.f32.f16.f16.f32 "
        "{%0,%1,%2,%3}, {%4,%5,%6,%7}, {%8,%9}, {%0,%1,%2,%3};"
        : "+f"(c[0]), "+f"(c[1]), "+f"(c[2]), "+f"(c[3])
        : "r"(a[0]), "r"(a[1]), "r"(a[2]), "r"(a[3]), "r"(b[0]), "r"(b[1]));
}

// ---------------- hand-rolled bit-exact e4m3 RNE quantization (PROVEN) --------
__device__ __forceinline__ float quant_e4m3_rne(float y) {
    float ay = fabsf(y);
    if (ay < 0.015625f) {                       // < 2^-6 : subnormal grid
        return rintf(y * 512.0f) * (1.0f / 512.0f);
    }
    int qe = (int)((__float_as_uint(ay) >> 23) & 0xFF) - 127;   // floor(log2 ay), exact
    float step = __uint_as_float((uint32_t)(qe - 3 + 127) << 23);   // 2^(qe-3)
    return rintf(y / step) * step;
}

// ---------------- quantize+dequantize prepass v2 (coalesced, fused) -----------
// 4 lanes per 32-elem MX block; lane sub handles float4s sub and sub+4.
// Group amax via shfl_xor within aligned 4-lane groups. Math identical to the
// proven v1 (same amax -> ex -> inv/scale -> e4m3 RNE -> f16 store).
#define XBLKS (M_DIM * KGRP)         // 1,048,576
#define WBLKS (N_DIM * KGRP)         // 524,288
#define XCTAS (XBLKS / 64)           // 16384 (64 MX blocks per 256-thread CTA)
#define WCTAS (WBLKS / 64)           // 8192

__global__ void __launch_bounds__(256) quant_dq2_kernel(const float* __restrict__ x,
                                                        const float* __restrict__ wgt) {
    int tid = threadIdx.x;
    int grp = blockIdx.x * 64 + (tid >> 2);
    int sub = tid & 3;
    const float* __restrict__ in;
    __half* __restrict__ outp;
    if (blockIdx.x < XCTAS) {
        in = x; outp = g_xdq;
    } else {
        grp -= XBLKS; in = wgt; outp = g_wdq;
    }

    const float4* p = reinterpret_cast<const float4*>(in) + (size_t)grp * 8 + sub;
    float4 v0 = p[0];
    float4 v1 = p[4];

    float amax = 1e-38f;
    amax = fmaxf(amax, fabsf(v0.x)); amax = fmaxf(amax, fabsf(v0.y));
    amax = fmaxf(amax, fabsf(v0.z)); amax = fmaxf(amax, fabsf(v0.w));
    amax = fmaxf(amax, fabsf(v1.x)); amax = fmaxf(amax, fabsf(v1.y));
    amax = fmaxf(amax, fabsf(v1.z)); amax = fmaxf(amax, fabsf(v1.w));
    amax = fmaxf(amax, __shfl_xor_sync(0xffffffffu, amax, 1));
    amax = fmaxf(amax, __shfl_xor_sync(0xffffffffu, amax, 2));

    int e = (int)((__float_as_uint(amax) >> 23) & 0xFF) - 127;  // floor(log2 amax), exact
    int ex = e - 8;
    ex = ex < -127 ? -127 : ex;
    float inv = __uint_as_float((uint32_t)(127 - ex) << 23);     // 2^-ex
    float scale = __uint_as_float((uint32_t)(ex + 127) << 23);   // 2^ex

    float f[8] = {v0.x, v0.y, v0.z, v0.w, v1.x, v1.y, v1.z, v1.w};
    uint32_t w[4];
#pragma unroll
    for (int j = 0; j < 4; j++) {
        float y0 = fminf(fmaxf(f[2 * j] * inv, -448.0f), 448.0f);
        float y1 = fminf(fmaxf(f[2 * j + 1] * inv, -448.0f), 448.0f);
        float dq0 = quant_e4m3_rne(y0) * scale;
        float dq1 = quant_e4m3_rne(y1) * scale;
        __half h0 = __float2half_rn(dq0);
        __half h1 = __float2half_rn(dq1);
        uint32_t lo = (uint32_t)*reinterpret_cast<uint16_t*>(&h0);
        uint32_t hi = (uint32_t)*reinterpret_cast<uint16_t*>(&h1);
        w[j] = lo | (hi << 16);
    }
    // lane sub writes halves [sub*8, sub*8+8) of the block -> matches f ordering:
    // f covers elements [sub*4, sub*4+4) and [sub*4+16, sub*4+20)... NO —
    // v0 = float4 #sub (elems 4sub..4sub+3), v1 = float4 #(sub+4) (elems 16+4sub..).
    // So w[0],w[1] hold elems 4sub..4sub+3 ; w[2],w[3] hold elems 16+4sub..16+4sub+3.
    uint2* op = reinterpret_cast<uint2*>(outp + (size_t)grp * 32);
    op[sub] = make_uint2(w[0], w[1]);           // elems 4sub..4sub+3
    op[sub + 4] = make_uint2(w[2], w[3]);       // elems 16+4sub..16+4sub+3
}

// ---------------- tensor-core GEMM: 128x128 tile, 2 CTAs/SM -------------------
// C[8192,4096] = A[8192,4096] * B[4096,4096]^T + bias.
// CTA tile 128(M) x 128(N), 256 threads (8 warps as 2x4, warp tile 64x32).
// K-chunk = 64 halves; padded smem rows RS=144B; ldmatrix.x4 fragments;
// 3-stage cp.async pipeline, SINGLE __syncthreads per chunk.
// OUTPUT: float32 values pre-rounded to the bf16 grid (proven convention).
#define TM 128
#define TN 128
#define KC 64
#define NCHUNK (K_DIM / KC)          // 64
#define RS 144                        // smem row stride in bytes
#define STAGE_A_BYTES (TM * RS)      // 18432
#define STAGE_B_BYTES (TN * RS)      // 18432
#define STAGE_BYTES (STAGE_A_BYTES + STAGE_B_BYTES)  // 36864
#define NSTAGE 3
#define GEMM_SMEM (NSTAGE * STAGE_BYTES)             // 110592 (108 KB) -> 2 CTAs/SM

__global__ void __launch_bounds__(256, 2)
mx_gemm_f16(const float* __restrict__ bias, float* __restrict__ out) {
    extern __shared__ char smem[];
    uint32_t sb = smem_u32(smem);
    int tid = threadIdx.x;
    int lane = tid & 31;
    int wid = tid >> 5;
    int wm = wid >> 2;     // 2 M-groups of 64
    int wn = wid & 3;      // 4 N-groups of 32
    int mtile = blockIdx.x, ntile = blockIdx.y;

    const char* Ab = (const char*)(g_xdq + (size_t)mtile * TM * K_DIM);
    const char* Bb = (const char*)(g_wdq + (size_t)ntile * TN * K_DIM);

    // ldmatrix.x4 lane->address mapping (PROVEN convention from R11/R12):
    uint32_t abase[4], bbase[2];
    {
        int arow_l = lane & 15;
        int aseg = (lane >> 4) & 1;
#pragma unroll
        for (int mf = 0; mf < 4; mf++)
            abase[mf] = (uint32_t)((wm * 64 + mf * 16 + arow_l) * RS + aseg * 16);
        int brow_l = (lane & 7) + ((lane & 16) ? 8 : 0);
        int bseg = (lane >> 3) & 1;
#pragma unroll
        for (int jp = 0; jp < 2; jp++)
            bbase[jp] = (uint32_t)(STAGE_A_BYTES + (wn * 32 + jp * 16 + brow_l) * RS + bseg * 16);
    }

    float acc[4][4][4];
#pragma unroll
    for (int i = 0; i < 4; i++)
#pragma unroll
        for (int j = 0; j < 4; j++)
#pragma unroll
            for (int k = 0; k < 4; k++) acc[i][j][k] = 0.f;

    // ---- async stage loader: A 128 rows + B 128 rows, 8 segs of 16B each ----
#define LOAD_STAGE(chunk, s)                                                            \
    do {                                                                                \
        uint32_t sa_ = sb + (s) * STAGE_BYTES;                                          \
        const char* ag_ = Ab + (size_t)(chunk) * 128;                                   \
        _Pragma("unroll")                                                               \
        for (int i_ = 0; i_ < 4; i_++) {                                                \
            int idx_ = tid + i_ * 256;                                                  \
            int row_ = idx_ >> 3, seg_ = idx_ & 7;                                      \
            cp_async16(sa_ + (uint32_t)(row_ * RS + seg_ * 16),                         \
                       ag_ + (size_t)row_ * (K_DIM * 2) + seg_ * 16);                   \
        }                                                                               \
        uint32_t sbm_ = sa_ + STAGE_A_BYTES;                                            \
        const char* bg_ = Bb + (size_t)(chunk) * 128;                                   \
        _Pragma("unroll")                                                               \
        for (int i_ = 0; i_ < 4; i_++) {                                                \
            int idx_ = tid + i_ * 256;                                                  \
            int row_ = idx_ >> 3, seg_ = idx_ & 7;                                      \
            cp_async16(sbm_ + (uint32_t)(row_ * RS + seg_ * 16),                        \
                       bg_ + (size_t)row_ * (K_DIM * 2) + seg_ * 16);                   \
        }                                                                               \
        asm volatile("cp.async.commit_group;" ::: "memory");                            \
    } while (0)

    // prologue: chunks 0,1 into stages 0,1
    LOAD_STAGE(0, 0);
    LOAD_STAGE(1, 1);

    // Stage indices cycle mod 3. At iter c: wait for chunk c, ONE sync, then
    // load chunk c+2 into stage (c+2)%3 (== stage read at iter c-1; the sync
    // orders all warps' reads of it before any warp's new cp.async writes).
    int s_cur = 0, s_nxt = 2;
    for (int c = 0; c < NCHUNK; c++) {
        asm volatile("cp.async.wait_group 1;" ::: "memory");   // chunk c complete
        __syncthreads();
        if (c + 2 < NCHUNK) {
            LOAD_STAGE(c + 2, s_nxt);
        } else {
            asm volatile("cp.async.commit_group;" ::: "memory");  // keep group count
        }

        uint32_t sa = sb + (uint32_t)s_cur * STAGE_BYTES;
#pragma unroll
        for (int kb = 0; kb < 4; kb++) {
            uint32_t kx = (uint32_t)(kb * 32);
            uint32_t a[4][4];
#pragma unroll
            for (int mf = 0; mf < 4; mf++)
                ldsm_x4(a[mf][0], a[mf][1], a[mf][2], a[mf][3], sa + abase[mf] + kx);
            uint32_t b[4][2];
#pragma unroll
            for (int jp = 0; jp < 2; jp++) {
                uint32_t r0, r1, r2, r3;
                ldsm_x4(r0, r1, r2, r3, sa + bbase[jp] + kx);
                b[2 * jp][0] = r0; b[2 * jp][1] = r1;
                b[2 * jp + 1][0] = r2; b[2 * jp + 1][1] = r3;
            }
#pragma unroll
            for (int mf = 0; mf < 4; mf++)
#pragma unroll
                for (int nf = 0; nf < 4; nf++) mma16816(acc[mf][nf], a[mf], b[nf]);
        }
        s_cur = s_cur == 2 ? 0 : s_cur + 1;
        s_nxt = s_nxt == 2 ? 0 : s_nxt + 1;
    }

    // ---- epilogue: + bias -> round to bf16 grid -> store f32 (PROVEN) ----
    int g = lane >> 2;
    int t = lane & 3;
    int ncol0 = ntile * TN + wn * 32 + t * 2;
    float2 bv[4];
#pragma unroll
    for (int nf = 0; nf < 4; nf++)
        bv[nf] = *reinterpret_cast<const float2*>(bias + ncol0 + nf * 8);

    size_t mrow0 = (size_t)mtile * TM + wm * 64 + g;
#pragma unroll
    for (int mf = 0; mf < 4; mf++) {
        size_t r0 = mrow0 + mf * 16;
        size_t r1 = r0 + 8;
#pragma unroll
        for (int nf = 0; nf < 4; nf++) {
            int n = ncol0 + nf * 8;
            float o0 = __bfloat162float(__float2bfloat16_rn(acc[mf][nf][0] + bv[nf].x));
            float o1 = __bfloat162float(__float2bfloat16_rn(acc[mf][nf][1] + bv[nf].y));
            float o2 = __bfloat162float(__float2bfloat16_rn(acc[mf][nf][2] + bv[nf].x));
            float o3 = __bfloat162float(__float2bfloat16_rn(acc[mf][nf][3] + bv[nf].y));
            *reinterpret_cast<float2*>(out + r0 * N_DIM + n) = make_float2(o0, o1);
            *reinterpret_cast<float2*>(out + r1 * N_DIM + n) = make_float2(o2, o3);
        }
    }
}

// ---------------- launch ----------------
extern "C" void kernel_launch(void* const* d_in, const int* in_sizes, int n_in,
                              void* d_out, int out_size) {
    (void)out_size;
    const float* x = nullptr;
    const float* w = nullptr;
    const float* bias = nullptr;
    for (int i = 0; i < n_in; i++) {
        if (in_sizes[i] == 33554432) x = (const float*)d_in[i];
        else if (in_sizes[i] == 16777216) w = (const float*)d_in[i];
        else if (in_sizes[i] == 4096) bias = (const float*)d_in[i];
    }
    if (!x) x = (const float*)d_in[0];
    if (!w) w = (const float*)d_in[1];
    if (!bias) bias = (const float*)d_in[2];
    float* out = (float*)d_out;   // f32 output (bf16-rounded values) — PROVEN

    cudaFuncSetAttribute(mx_gemm_f16, cudaFuncAttributeMaxDynamicSharedMemorySize, GEMM_SMEM);

    quant_dq2_kernel<<<XCTAS + WCTAS, 256>>>(x, w);

    dim3 grid(M_DIM / TM, N_DIM / TN);   // 64 x 32
    mx_gemm_f16<<<grid, 256, GEMM_SMEM>>>(bias, out);
}